// round 7
// baseline (speedup 1.0000x reference)
#include <cuda_runtime.h>
#include <cuda_bf16.h>
#include <cstdint>

#define BB 2
#define SS 2048
#define DD 512
#define HH 8
#define LR 7
#define MTOT (BB*SS)        // 4096
#define K3 (3*DD)           // 1536

// scratch
__device__ float g_q[MTOT * DD];
__device__ float g_k[MTOT * DD];
__device__ float2 g_w2[MTOT * 128];         // [b*S+i][h*16+jj] duplicated (w,w) weights
__device__ __nv_bfloat16 g_a3[MTOT * K3];   // [hi | lo | hi] along K
__device__ __nv_bfloat16 g_b3q[DD * K3];    // [hi | hi | lo] along K, rows = n
__device__ __nv_bfloat16 g_b3k[DD * K3];

#define SWZ128(off) ((off) ^ (((off) >> 3) & 0x70))

__device__ __forceinline__ uint32_t smem_u32(const void* p) {
    uint32_t a;
    asm("{ .reg .u64 t; cvta.to.shared.u64 t, %1; cvt.u32.u64 %0, t; }" : "=r"(a) : "l"(p));
    return a;
}
__device__ __forceinline__ void cp16(uint32_t s, const void* g) {
    asm volatile("cp.async.cg.shared.global [%0], [%1], 16;" :: "r"(s), "l"(g));
}
#define CP_COMMIT() asm volatile("cp.async.commit_group;" ::: "memory")

__device__ __forceinline__ void ldm_x4(uint32_t& r0, uint32_t& r1, uint32_t& r2, uint32_t& r3, uint32_t a) {
    asm volatile("ldmatrix.sync.aligned.m8n8.x4.shared.b16 {%0,%1,%2,%3}, [%4];"
                 : "=r"(r0), "=r"(r1), "=r"(r2), "=r"(r3) : "r"(a));
}
__device__ __forceinline__ void ldm_x2(uint32_t& r0, uint32_t& r1, uint32_t a) {
    asm volatile("ldmatrix.sync.aligned.m8n8.x2.shared.b16 {%0,%1}, [%2];"
                 : "=r"(r0), "=r"(r1) : "r"(a));
}
__device__ __forceinline__ void mma16816(float* d, const uint32_t* a, const uint32_t* b) {
    asm volatile("mma.sync.aligned.m16n8k16.row.col.f32.bf16.bf16.f32 "
                 "{%0,%1,%2,%3}, {%4,%5,%6,%7}, {%8,%9}, {%0,%1,%2,%3};"
                 : "+f"(d[0]), "+f"(d[1]), "+f"(d[2]), "+f"(d[3])
                 : "r"(a[0]), "r"(a[1]), "r"(a[2]), "r"(a[3]), "r"(b[0]), "r"(b[1]));
}

// packed f32x2 helpers (sm_100+ base ISA)
__device__ __forceinline__ unsigned long long lds64(uint32_t a) {
    unsigned long long v;
    asm("ld.shared.b64 %0, [%1];" : "=l"(v) : "r"(a));
    return v;
}
__device__ __forceinline__ void lds_v2b64(unsigned long long& x, unsigned long long& y, uint32_t a) {
    asm("ld.shared.v2.b64 {%0,%1}, [%2];" : "=l"(x), "=l"(y) : "r"(a));
}
__device__ __forceinline__ void fma2(unsigned long long& d, unsigned long long a, unsigned long long b) {
    asm("fma.rn.f32x2 %0, %1, %2, %0;" : "+l"(d) : "l"(a), "l"(b));
}
__device__ __forceinline__ void stg_v2b64(void* p, unsigned long long x, unsigned long long y) {
    asm volatile("st.global.v2.b64 [%0], {%1,%2};" :: "l"(p), "l"(x), "l"(y) : "memory");
}

// ---------------------------------------------------------------------------
// split hidden_states into bf16 hi/lo, tripled K layout [hi|lo|hi]
// ---------------------------------------------------------------------------
__global__ void split_hs(const float* __restrict__ hs) {
    int idx = blockIdx.x * 256 + threadIdx.x;
    int m = idx >> 7;
    int c = idx & 127;
    float4 v = ((const float4*)hs)[idx];
    __nv_bfloat16 hx = __float2bfloat16(v.x), hy = __float2bfloat16(v.y);
    __nv_bfloat16 hz = __float2bfloat16(v.z), hw = __float2bfloat16(v.w);
    __nv_bfloat16 lx = __float2bfloat16(v.x - __bfloat162float(hx));
    __nv_bfloat16 ly = __float2bfloat16(v.y - __bfloat162float(hy));
    __nv_bfloat16 lz = __float2bfloat16(v.z - __bfloat162float(hz));
    __nv_bfloat16 lw = __float2bfloat16(v.w - __bfloat162float(hw));
    __nv_bfloat162 H0; H0.x = hx; H0.y = hy;
    __nv_bfloat162 H1; H1.x = hz; H1.y = hw;
    __nv_bfloat162 L0; L0.x = lx; L0.y = ly;
    __nv_bfloat162 L1; L1.x = lz; L1.y = lw;
    __nv_bfloat16* p = g_a3 + (size_t)m * K3 + 4 * c;
    *(__nv_bfloat162*)(p)          = H0; *(__nv_bfloat162*)(p + 2)          = H1;
    *(__nv_bfloat162*)(p + DD)     = L0; *(__nv_bfloat162*)(p + DD + 2)     = L1;
    *(__nv_bfloat162*)(p + 2*DD)   = H0; *(__nv_bfloat162*)(p + 2*DD + 2)   = H1;
}

// ---------------------------------------------------------------------------
// split + transpose W (stored [k, n]) into B3 [n, 3K] = [hi|hi|lo]
// ---------------------------------------------------------------------------
__global__ void split_w(const float* __restrict__ Wq, const float* __restrict__ Wk) {
    __shared__ float t[32][33];
    const float* W = blockIdx.z ? Wk : Wq;
    __nv_bfloat16* B3 = blockIdx.z ? g_b3k : g_b3q;
    int n0 = blockIdx.x * 32, k0 = blockIdx.y * 32;
    int tx = threadIdx.x, ty = threadIdx.y;
#pragma unroll
    for (int r = 0; r < 4; r++)
        t[ty + r * 8][tx] = W[(size_t)(k0 + ty + r * 8) * DD + n0 + tx];
    __syncthreads();
#pragma unroll
    for (int r = 0; r < 4; r++) {
        int n = n0 + ty + r * 8, k = k0 + tx;
        float v = t[tx][ty + r * 8];
        __nv_bfloat16 h = __float2bfloat16(v);
        __nv_bfloat16 l = __float2bfloat16(v - __bfloat162float(h));
        B3[(size_t)n * K3 + k]        = h;
        B3[(size_t)n * K3 + DD + k]   = h;
        B3[(size_t)n * K3 + 2*DD + k] = l;
    }
}

// ---------------------------------------------------------------------------
// mma.sync bf16 GEMM: C[4096,512] = A3[4096,1536] * B3[512,1536]^T, f32 acc
// ---------------------------------------------------------------------------
#define MT 128
#define NT 128
#define KT 64
#define NK 24
#define STG 32768u
#define NSTG 3
#define GEMM_SMEM (NSTG * STG)

__device__ __forceinline__ void load_tile(int tile, int stg,
                                          const char* Ab, const char* Bb,
                                          uint32_t sb, int tid) {
    size_t koff = (size_t)tile * (KT * 2);
    uint32_t sA = sb + (uint32_t)stg * STG;
    uint32_t sB = sA + 16384u;
#pragma unroll
    for (int c = 0; c < 4; c++) {
        int q = tid + c * 256;
        int r = q >> 3, col = (q & 7) * 16;
        cp16(sA + SWZ128(r * 128 + col), Ab + (size_t)r * (K3 * 2) + koff + col);
    }
#pragma unroll
    for (int c = 0; c < 4; c++) {
        int q = tid + c * 256;
        int r = q >> 3, col = (q & 7) * 16;
        cp16(sB + SWZ128(r * 128 + col), Bb + (size_t)r * (K3 * 2) + koff + col);
    }
}

__global__ __launch_bounds__(256, 2)
void gemm3() {
    extern __shared__ char smem[];
    uint32_t sb = smem_u32(smem);
    const int tid = threadIdx.x, wid = tid >> 5, lane = tid & 31;
    const int m0 = blockIdx.x * MT;
    const int n0 = blockIdx.y * NT;
    const __nv_bfloat16* B3 = blockIdx.z ? g_b3k : g_b3q;
    float* C = blockIdx.z ? g_k : g_q;

    const char* Ab = (const char*)g_a3 + (size_t)m0 * (K3 * 2);
    const char* Bb = (const char*)B3 + (size_t)n0 * (K3 * 2);

    const int wm = wid & 1;
    const int wn = wid >> 1;

    float acc[4][4][4];
#pragma unroll
    for (int i = 0; i < 4; i++)
#pragma unroll
        for (int j = 0; j < 4; j++)
#pragma unroll
            for (int r = 0; r < 4; r++) acc[i][j][r] = 0.f;

    load_tile(0, 0, Ab, Bb, sb, tid); CP_COMMIT();
    load_tile(1, 1, Ab, Bb, sb, tid); CP_COMMIT();

    const int a_row = wm * 64 + (lane & 15);
    const int a_cg  = (lane >> 4) * 16;
    const int b_row = wn * 32 + (lane & 7);
    const int b_cg  = ((lane >> 3) & 1) * 16;

    for (int t = 0; t < NK; t++) {
        asm volatile("cp.async.wait_group 1;" ::: "memory");
        __syncthreads();

        if (t + 2 < NK)
            load_tile(t + 2, (t + 2) % NSTG, Ab, Bb, sb, tid);
        CP_COMMIT();

        uint32_t sA = sb + (uint32_t)(t % NSTG) * STG;
        uint32_t sB = sA + 16384u;
#pragma unroll
        for (int ks = 0; ks < 4; ks++) {
            uint32_t af[4][4], bf[4][2];
#pragma unroll
            for (int mi = 0; mi < 4; mi++)
                ldm_x4(af[mi][0], af[mi][1], af[mi][2], af[mi][3],
                       sA + SWZ128((a_row + mi * 16) * 128 + ks * 32 + a_cg));
#pragma unroll
            for (int ni = 0; ni < 4; ni++)
                ldm_x2(bf[ni][0], bf[ni][1],
                       sB + SWZ128((b_row + ni * 8) * 128 + ks * 32 + b_cg));
#pragma unroll
            for (int mi = 0; mi < 4; mi++)
#pragma unroll
                for (int ni = 0; ni < 4; ni++)
                    mma16816(acc[mi][ni], af[mi], bf[ni]);
        }
    }

    const int er = lane >> 2;
    const int ec = (lane & 3) * 2;
#pragma unroll
    for (int mi = 0; mi < 4; mi++) {
        int r0 = m0 + wm * 64 + mi * 16 + er;
#pragma unroll
        for (int ni = 0; ni < 4; ni++) {
            int cc = n0 + wn * 32 + ni * 8 + ec;
            *(float2*)(C + (size_t)r0 * DD + cc) = make_float2(acc[mi][ni][0], acc[mi][ni][1]);
            *(float2*)(C + (size_t)(r0 + 8) * DD + cc) = make_float2(acc[mi][ni][2], acc[mi][ni][3]);
        }
    }
}

// ---------------------------------------------------------------------------
// wts v3: block = 8 consecutive i, k rows staged in smem (swizzled).
// warp = one i; lane owns 16 floats of head (lane>>2): float4 idx 16h+g+4t.
// Swizzle: flip bit2 of inner idx for odd heads -> conflict-free LDS.128.
// Writes duplicated (w,w) float2 weights for the packed-fma ctx kernel.
// ---------------------------------------------------------------------------
#define WTS_SMEM (22 * DD * 4)    // 45056

__global__ __launch_bounds__(256)
void wts() {
    extern __shared__ float sk[];           // [22][512], swizzled
    float4* sk4 = (float4*)sk;

    const int b = blockIdx.y;
    const int i0 = blockIdx.x * 8;
    const int tid = threadIdx.x;

    // stage 22 clamped k rows
    for (int idx = tid; idx < 22 * 128; idx += 256) {
        int r = idx >> 7, p = idx & 127;
        int j = i0 - LR + r;
        j = j < 0 ? 0 : (j >= SS ? SS - 1 : j);
        int ps = p ^ (((p >> 4) & 1) << 2);
        sk4[r * 128 + ps] = ((const float4*)(g_k + ((size_t)b * SS + j) * DD))[p];
    }
    __syncthreads();

    const int wid = tid >> 5, lane = tid & 31;
    const int i = i0 + wid;
    const int h = lane >> 2, g = lane & 3;
    const int flip = (h & 1) << 2;

    const float4* q4 = (const float4*)(g_q + ((size_t)b * SS + i) * DD);
    float4 ql[4];
#pragma unroll
    for (int t = 0; t < 4; t++) ql[t] = q4[16 * h + g + 4 * t];

    float sc[15];
#pragma unroll
    for (int jj = 0; jj < 15; jj++) {
        int j = i - LR + jj;
        bool valid = (j >= 0) && (j < SS);
        const float4* kr = sk4 + (wid + jj) * 128;
        float p = 0.f;
#pragma unroll
        for (int t = 0; t < 4; t++) {
            float4 kv = kr[(16 * h + g + 4 * t) ^ flip];
            p += ql[t].x * kv.x + ql[t].y * kv.y + ql[t].z * kv.z + ql[t].w * kv.w;
        }
        p += __shfl_xor_sync(0xffffffffu, p, 1);
        p += __shfl_xor_sync(0xffffffffu, p, 2);
        sc[jj] = valid ? p * 0.125f : -1e30f;
    }

    float m = -1e30f;
#pragma unroll
    for (int jj = 0; jj < 15; jj++) m = fmaxf(m, sc[jj]);
    float s = 0.f;
#pragma unroll
    for (int jj = 0; jj < 15; jj++) { sc[jj] = __expf(sc[jj] - m); s += sc[jj]; }
    float inv = 1.f / s;

    float2* wp = g_w2 + (((size_t)b * SS + i) << 7) + h * 16;
#pragma unroll
    for (int jj = g; jj < 15; jj += 4) {
        float w = sc[jj] * inv;
        wp[jj] = make_float2(w, w);
    }
}

// ---------------------------------------------------------------------------
// ctx v3: out[b,h,i,:] = sum_jj w * hs[b, i-7+jj, :], packed fma.rn.f32x2
// block = 32 i x 512 d for one b; grid (64, 2); 126 KB smem, 1 CTA/SM
// ---------------------------------------------------------------------------
#define CTX_SMEM (46 * DD * 4 + 32 * 128 * 8)   // 94208 + 32768 = 126976

__global__ __launch_bounds__(256, 1)
void ctx(const float* __restrict__ hs, float* __restrict__ out) {
    extern __shared__ char smemraw[];
    float* sh = (float*)smemraw;                          // [46][512]
    float2* sw = (float2*)(smemraw + 46 * DD * 4);        // [32][128]

    const int ic = blockIdx.x, b = blockIdx.y;
    const int i0 = ic * 32;
    const int tid = threadIdx.x;

    for (int idx = tid; idx < 46 * 128; idx += 256) {
        int r = idx >> 7, c = idx & 127;
        int j = i0 - LR + r;
        j = j < 0 ? 0 : (j >= SS ? SS - 1 : j);
        ((float4*)sh)[idx] = ((const float4*)(hs + ((size_t)b * SS + j) * DD))[c];
    }
    {
        const float4* gw4 = (const float4*)(g_w2 + (((size_t)b * SS + i0) << 7));
        for (int idx = tid; idx < 2048; idx += 256)
            ((float4*)sw)[idx] = gw4[idx];
    }
    __syncthreads();

    const int wid = tid >> 5, lane = tid & 31;
    const uint32_t shb = smem_u32(sh);
    const uint32_t swb = smem_u32(sw);

#pragma unroll
    for (int ii = 0; ii < 4; ii++) {
        const int il = ii * 8 + wid;
        const int ig = i0 + il;
        const uint32_t wbase = swb + (uint32_t)il * 1024;      // il*128 float2
#pragma unroll
        for (int cp = 0; cp < 4; cp++) {
            const int c4 = lane + 32 * cp;                     // float4 col 0..127
            unsigned long long acc[HH][2];
#pragma unroll
            for (int h = 0; h < HH; h++) { acc[h][0] = 0ull; acc[h][1] = 0ull; }
#pragma unroll
            for (int jj = 0; jj < 15; jj++) {
                unsigned long long v0, v1;
                lds_v2b64(v0, v1, shb + ((il + jj) * 128 + c4) * 16);
#pragma unroll
                for (int h = 0; h < HH; h++) {
                    unsigned long long w = lds64(wbase + (h * 16 + jj) * 8);
                    fma2(acc[h][0], w, v0);
                    fma2(acc[h][1], w, v1);
                }
            }
#pragma unroll
            for (int h = 0; h < HH; h++)
                stg_v2b64(out + (((size_t)b * HH + h) * SS + ig) * DD + c4 * 4,
                          acc[h][0], acc[h][1]);
        }
    }
}

// ---------------------------------------------------------------------------
extern "C" void kernel_launch(void* const* d_in, const int* in_sizes, int n_in,
                              void* d_out, int out_size) {
    const float* hs = (const float*)d_in[0];
    const float* Wq = (const float*)d_in[1];
    const float* Wk = (const float*)d_in[2];
    float* out = (float*)d_out;

    cudaFuncSetAttribute(gemm3, cudaFuncAttributeMaxDynamicSharedMemorySize, GEMM_SMEM);
    cudaFuncSetAttribute(ctx, cudaFuncAttributeMaxDynamicSharedMemorySize, CTX_SMEM);
    cudaFuncSetAttribute(wts, cudaFuncAttributeMaxDynamicSharedMemorySize, WTS_SMEM);

    split_hs<<<2048, 256>>>(hs);
    split_w<<<dim3(16, 16, 2), dim3(32, 8)>>>(Wq, Wk);
    gemm3<<<dim3(32, 4, 2), 256, GEMM_SMEM>>>();
    wts<<<dim3(SS / 8, BB), 256, WTS_SMEM>>>();
    ctx<<<dim3(64, 2), 256, CTX_SMEM>>>(hs, out);
}

// round 8
// speedup vs baseline: 1.0610x; 1.0610x over previous
#include <cuda_runtime.h>
#include <cuda_bf16.h>
#include <cstdint>

#define BB 2
#define SS 2048
#define DD 512
#define HH 8
#define LR 7
#define MTOT (BB*SS)        // 4096
#define K3 (3*DD)           // 1536

// scratch
__device__ float g_q[MTOT * DD];
__device__ float g_k[MTOT * DD];
__device__ float2 g_w2[MTOT * 128];         // [b*S+i][jj*8+h] duplicated (w,w) weights
__device__ __nv_bfloat16 g_a3[MTOT * K3];   // [hi | lo | hi] along K
__device__ __nv_bfloat16 g_b3q[DD * K3];    // [hi | hi | lo] along K, rows = n
__device__ __nv_bfloat16 g_b3k[DD * K3];

#define SWZ128(off) ((off) ^ (((off) >> 3) & 0x70))

__device__ __forceinline__ uint32_t smem_u32(const void* p) {
    uint32_t a;
    asm("{ .reg .u64 t; cvta.to.shared.u64 t, %1; cvt.u32.u64 %0, t; }" : "=r"(a) : "l"(p));
    return a;
}
__device__ __forceinline__ void cp16(uint32_t s, const void* g) {
    asm volatile("cp.async.cg.shared.global [%0], [%1], 16;" :: "r"(s), "l"(g));
}
#define CP_COMMIT() asm volatile("cp.async.commit_group;" ::: "memory")

__device__ __forceinline__ void ldm_x4(uint32_t& r0, uint32_t& r1, uint32_t& r2, uint32_t& r3, uint32_t a) {
    asm volatile("ldmatrix.sync.aligned.m8n8.x4.shared.b16 {%0,%1,%2,%3}, [%4];"
                 : "=r"(r0), "=r"(r1), "=r"(r2), "=r"(r3) : "r"(a));
}
__device__ __forceinline__ void ldm_x2(uint32_t& r0, uint32_t& r1, uint32_t a) {
    asm volatile("ldmatrix.sync.aligned.m8n8.x2.shared.b16 {%0,%1}, [%2];"
                 : "=r"(r0), "=r"(r1) : "r"(a));
}
__device__ __forceinline__ void mma16816(float* d, const uint32_t* a, const uint32_t* b) {
    asm volatile("mma.sync.aligned.m16n8k16.row.col.f32.bf16.bf16.f32 "
                 "{%0,%1,%2,%3}, {%4,%5,%6,%7}, {%8,%9}, {%0,%1,%2,%3};"
                 : "+f"(d[0]), "+f"(d[1]), "+f"(d[2]), "+f"(d[3])
                 : "r"(a[0]), "r"(a[1]), "r"(a[2]), "r"(a[3]), "r"(b[0]), "r"(b[1]));
}

// packed f32x2 helpers (sm_100+ base ISA; compiled OK in prior round)
__device__ __forceinline__ void lds_v2b64(unsigned long long& x, unsigned long long& y, uint32_t a) {
    asm("ld.shared.v2.b64 {%0,%1}, [%2];" : "=l"(x), "=l"(y) : "r"(a));
}
__device__ __forceinline__ void fma2(unsigned long long& d, unsigned long long a, unsigned long long b) {
    asm("fma.rn.f32x2 %0, %1, %2, %0;" : "+l"(d) : "l"(a), "l"(b));
}
__device__ __forceinline__ void stg_v2b64(void* p, unsigned long long x, unsigned long long y) {
    asm volatile("st.global.v2.b64 [%0], {%1,%2};" :: "l"(p), "l"(x), "l"(y) : "memory");
}

// ---------------------------------------------------------------------------
// split hidden_states into bf16 hi/lo, tripled K layout [hi|lo|hi]
// ---------------------------------------------------------------------------
__global__ void split_hs(const float* __restrict__ hs) {
    int idx = blockIdx.x * 256 + threadIdx.x;
    int m = idx >> 7;
    int c = idx & 127;
    float4 v = ((const float4*)hs)[idx];
    __nv_bfloat16 hx = __float2bfloat16(v.x), hy = __float2bfloat16(v.y);
    __nv_bfloat16 hz = __float2bfloat16(v.z), hw = __float2bfloat16(v.w);
    __nv_bfloat16 lx = __float2bfloat16(v.x - __bfloat162float(hx));
    __nv_bfloat16 ly = __float2bfloat16(v.y - __bfloat162float(hy));
    __nv_bfloat16 lz = __float2bfloat16(v.z - __bfloat162float(hz));
    __nv_bfloat16 lw = __float2bfloat16(v.w - __bfloat162float(hw));
    __nv_bfloat162 H0; H0.x = hx; H0.y = hy;
    __nv_bfloat162 H1; H1.x = hz; H1.y = hw;
    __nv_bfloat162 L0; L0.x = lx; L0.y = ly;
    __nv_bfloat162 L1; L1.x = lz; L1.y = lw;
    __nv_bfloat16* p = g_a3 + (size_t)m * K3 + 4 * c;
    *(__nv_bfloat162*)(p)          = H0; *(__nv_bfloat162*)(p + 2)          = H1;
    *(__nv_bfloat162*)(p + DD)     = L0; *(__nv_bfloat162*)(p + DD + 2)     = L1;
    *(__nv_bfloat162*)(p + 2*DD)   = H0; *(__nv_bfloat162*)(p + 2*DD + 2)   = H1;
}

// ---------------------------------------------------------------------------
// split + transpose W (stored [k, n]) into B3 [n, 3K] = [hi|hi|lo]
// ---------------------------------------------------------------------------
__global__ void split_w(const float* __restrict__ Wq, const float* __restrict__ Wk) {
    __shared__ float t[32][33];
    const float* W = blockIdx.z ? Wk : Wq;
    __nv_bfloat16* B3 = blockIdx.z ? g_b3k : g_b3q;
    int n0 = blockIdx.x * 32, k0 = blockIdx.y * 32;
    int tx = threadIdx.x, ty = threadIdx.y;
#pragma unroll
    for (int r = 0; r < 4; r++)
        t[ty + r * 8][tx] = W[(size_t)(k0 + ty + r * 8) * DD + n0 + tx];
    __syncthreads();
#pragma unroll
    for (int r = 0; r < 4; r++) {
        int n = n0 + ty + r * 8, k = k0 + tx;
        float v = t[tx][ty + r * 8];
        __nv_bfloat16 h = __float2bfloat16(v);
        __nv_bfloat16 l = __float2bfloat16(v - __bfloat162float(h));
        B3[(size_t)n * K3 + k]        = h;
        B3[(size_t)n * K3 + DD + k]   = h;
        B3[(size_t)n * K3 + 2*DD + k] = l;
    }
}

// ---------------------------------------------------------------------------
// mma.sync bf16 GEMM: C[4096,512] = A3[4096,1536] * B3[512,1536]^T, f32 acc
// ---------------------------------------------------------------------------
#define MT 128
#define NT 128
#define KT 64
#define NK 24
#define STG 32768u
#define NSTG 3
#define GEMM_SMEM (NSTG * STG)

__device__ __forceinline__ void load_tile(int tile, int stg,
                                          const char* Ab, const char* Bb,
                                          uint32_t sb, int tid) {
    size_t koff = (size_t)tile * (KT * 2);
    uint32_t sA = sb + (uint32_t)stg * STG;
    uint32_t sB = sA + 16384u;
#pragma unroll
    for (int c = 0; c < 4; c++) {
        int q = tid + c * 256;
        int r = q >> 3, col = (q & 7) * 16;
        cp16(sA + SWZ128(r * 128 + col), Ab + (size_t)r * (K3 * 2) + koff + col);
    }
#pragma unroll
    for (int c = 0; c < 4; c++) {
        int q = tid + c * 256;
        int r = q >> 3, col = (q & 7) * 16;
        cp16(sB + SWZ128(r * 128 + col), Bb + (size_t)r * (K3 * 2) + koff + col);
    }
}

__global__ __launch_bounds__(256, 2)
void gemm3() {
    extern __shared__ char smem[];
    uint32_t sb = smem_u32(smem);
    const int tid = threadIdx.x, wid = tid >> 5, lane = tid & 31;
    const int m0 = blockIdx.x * MT;
    const int n0 = blockIdx.y * NT;
    const __nv_bfloat16* B3 = blockIdx.z ? g_b3k : g_b3q;
    float* C = blockIdx.z ? g_k : g_q;

    const char* Ab = (const char*)g_a3 + (size_t)m0 * (K3 * 2);
    const char* Bb = (const char*)B3 + (size_t)n0 * (K3 * 2);

    const int wm = wid & 1;
    const int wn = wid >> 1;

    float acc[4][4][4];
#pragma unroll
    for (int i = 0; i < 4; i++)
#pragma unroll
        for (int j = 0; j < 4; j++)
#pragma unroll
            for (int r = 0; r < 4; r++) acc[i][j][r] = 0.f;

    load_tile(0, 0, Ab, Bb, sb, tid); CP_COMMIT();
    load_tile(1, 1, Ab, Bb, sb, tid); CP_COMMIT();

    const int a_row = wm * 64 + (lane & 15);
    const int a_cg  = (lane >> 4) * 16;
    const int b_row = wn * 32 + (lane & 7);
    const int b_cg  = ((lane >> 3) & 1) * 16;

    for (int t = 0; t < NK; t++) {
        asm volatile("cp.async.wait_group 1;" ::: "memory");
        __syncthreads();

        if (t + 2 < NK)
            load_tile(t + 2, (t + 2) % NSTG, Ab, Bb, sb, tid);
        CP_COMMIT();

        uint32_t sA = sb + (uint32_t)(t % NSTG) * STG;
        uint32_t sB = sA + 16384u;
#pragma unroll
        for (int ks = 0; ks < 4; ks++) {
            uint32_t af[4][4], bf[4][2];
#pragma unroll
            for (int mi = 0; mi < 4; mi++)
                ldm_x4(af[mi][0], af[mi][1], af[mi][2], af[mi][3],
                       sA + SWZ128((a_row + mi * 16) * 128 + ks * 32 + a_cg));
#pragma unroll
            for (int ni = 0; ni < 4; ni++)
                ldm_x2(bf[ni][0], bf[ni][1],
                       sB + SWZ128((b_row + ni * 8) * 128 + ks * 32 + b_cg));
#pragma unroll
            for (int mi = 0; mi < 4; mi++)
#pragma unroll
                for (int ni = 0; ni < 4; ni++)
                    mma16816(acc[mi][ni], af[mi], bf[ni]);
        }
    }

    const int er = lane >> 2;
    const int ec = (lane & 3) * 2;
#pragma unroll
    for (int mi = 0; mi < 4; mi++) {
        int r0 = m0 + wm * 64 + mi * 16 + er;
#pragma unroll
        for (int ni = 0; ni < 4; ni++) {
            int cc = n0 + wn * 32 + ni * 8 + ec;
            *(float2*)(C + (size_t)r0 * DD + cc) = make_float2(acc[mi][ni][0], acc[mi][ni][1]);
            *(float2*)(C + (size_t)(r0 + 8) * DD + cc) = make_float2(acc[mi][ni][2], acc[mi][ni][3]);
        }
    }
}

// ---------------------------------------------------------------------------
// wts v4: block = 16 consecutive i (512 thr), 30 k rows staged in smem.
// warp = one i; lane owns 16 floats of head (lane>>2).
// Writes duplicated (w,w) float2 weights, TRANSPOSED layout [i][jj*8+h].
// ---------------------------------------------------------------------------
#define WTS_SMEM (30 * DD * 4)    // 61440

__global__ __launch_bounds__(512)
void wts() {
    extern __shared__ float sk[];           // [30][512], swizzled
    float4* sk4 = (float4*)sk;

    const int b = blockIdx.y;
    const int i0 = blockIdx.x * 16;
    const int tid = threadIdx.x;

    for (int idx = tid; idx < 30 * 128; idx += 512) {
        int r = idx >> 7, p = idx & 127;
        int j = i0 - LR + r;
        j = j < 0 ? 0 : (j >= SS ? SS - 1 : j);
        int ps = p ^ (((p >> 4) & 1) << 2);
        sk4[r * 128 + ps] = ((const float4*)(g_k + ((size_t)b * SS + j) * DD))[p];
    }
    __syncthreads();

    const int wid = tid >> 5, lane = tid & 31;
    const int i = i0 + wid;
    const int h = lane >> 2, g = lane & 3;
    const int flip = (h & 1) << 2;

    const float4* q4 = (const float4*)(g_q + ((size_t)b * SS + i) * DD);
    float4 ql[4];
#pragma unroll
    for (int t = 0; t < 4; t++) ql[t] = q4[16 * h + g + 4 * t];

    float sc[15];
#pragma unroll
    for (int jj = 0; jj < 15; jj++) {
        int j = i - LR + jj;
        bool valid = (j >= 0) && (j < SS);
        const float4* kr = sk4 + (wid + jj) * 128;
        float p = 0.f;
#pragma unroll
        for (int t = 0; t < 4; t++) {
            float4 kv = kr[(16 * h + g + 4 * t) ^ flip];
            p += ql[t].x * kv.x + ql[t].y * kv.y + ql[t].z * kv.z + ql[t].w * kv.w;
        }
        p += __shfl_xor_sync(0xffffffffu, p, 1);
        p += __shfl_xor_sync(0xffffffffu, p, 2);
        sc[jj] = valid ? p * 0.125f : -1e30f;
    }

    float m = -1e30f;
#pragma unroll
    for (int jj = 0; jj < 15; jj++) m = fmaxf(m, sc[jj]);
    float s = 0.f;
#pragma unroll
    for (int jj = 0; jj < 15; jj++) { sc[jj] = __expf(sc[jj] - m); s += sc[jj]; }
    float inv = 1.f / s;

    float2* wp = g_w2 + (((size_t)b * SS + i) << 7);
#pragma unroll
    for (int jj = g; jj < 15; jj += 4) {
        float w = sc[jj] * inv;
        wp[jj * 8 + h] = make_float2(w, w);
    }
}

// ---------------------------------------------------------------------------
// ctx v4: out[b,h,i,:] = sum_jj w * hs[b, i-7+jj, :], packed fma.rn.f32x2
// block = 32 i x 256 d; grid (64, 2, 2); 78 KB smem -> 2 CTAs/SM
// weights [il][jj*8+h] float2 in smem: per jj, 4x ld.shared.v2.b64 broadcasts
// ---------------------------------------------------------------------------
#define CTX_SMEM (46 * 256 * 4 + 32 * 128 * 8)   // 47104 + 32768 = 79872

__global__ __launch_bounds__(256, 2)
void ctx(const float* __restrict__ hs, float* __restrict__ out) {
    extern __shared__ char smemraw[];
    float* sh = (float*)smemraw;                          // [46][256]
    float2* sw = (float2*)(smemraw + 46 * 256 * 4);       // [32][128] (jj*8+h)

    const int ic = blockIdx.x, dc = blockIdx.y, b = blockIdx.z;
    const int i0 = ic * 32, d0 = dc * 256;
    const int tid = threadIdx.x;

    for (int idx = tid; idx < 46 * 64; idx += 256) {
        int r = idx >> 6, c = idx & 63;
        int j = i0 - LR + r;
        j = j < 0 ? 0 : (j >= SS ? SS - 1 : j);
        ((float4*)sh)[idx] = ((const float4*)(hs + ((size_t)b * SS + j) * DD + d0))[c];
    }
    {
        const float4* gw4 = (const float4*)(g_w2 + (((size_t)b * SS + i0) << 7));
        for (int idx = tid; idx < 2048; idx += 256)
            ((float4*)sw)[idx] = gw4[idx];
    }
    __syncthreads();

    const int wid = tid >> 5, lane = tid & 31;
    const uint32_t shb = smem_u32(sh);
    const uint32_t swb = smem_u32(sw);

#pragma unroll
    for (int ii = 0; ii < 4; ii++) {
        const int il = ii * 8 + wid;
        const int ig = i0 + il;
        const uint32_t wbase = swb + (uint32_t)il * 1024;      // il*128 float2
#pragma unroll
        for (int cp = 0; cp < 2; cp++) {
            const int c4 = lane + 32 * cp;                     // float4 col 0..63
            unsigned long long acc[HH][2];
#pragma unroll
            for (int h = 0; h < HH; h++) { acc[h][0] = 0ull; acc[h][1] = 0ull; }
#pragma unroll
            for (int jj = 0; jj < 15; jj++) {
                unsigned long long v0, v1;
                lds_v2b64(v0, v1, shb + ((il + jj) * 64 + c4) * 16);
                unsigned long long w0, w1, w2, w3, w4, w5, w6, w7;
                lds_v2b64(w0, w1, wbase + jj * 64);
                lds_v2b64(w2, w3, wbase + jj * 64 + 16);
                lds_v2b64(w4, w5, wbase + jj * 64 + 32);
                lds_v2b64(w6, w7, wbase + jj * 64 + 48);
                fma2(acc[0][0], w0, v0); fma2(acc[0][1], w0, v1);
                fma2(acc[1][0], w1, v0); fma2(acc[1][1], w1, v1);
                fma2(acc[2][0], w2, v0); fma2(acc[2][1], w2, v1);
                fma2(acc[3][0], w3, v0); fma2(acc[3][1], w3, v1);
                fma2(acc[4][0], w4, v0); fma2(acc[4][1], w4, v1);
                fma2(acc[5][0], w5, v0); fma2(acc[5][1], w5, v1);
                fma2(acc[6][0], w6, v0); fma2(acc[6][1], w6, v1);
                fma2(acc[7][0], w7, v0); fma2(acc[7][1], w7, v1);
            }
#pragma unroll
            for (int h = 0; h < HH; h++)
                stg_v2b64(out + (((size_t)b * HH + h) * SS + ig) * DD + d0 + c4 * 4,
                          acc[h][0], acc[h][1]);
        }
    }
}

// ---------------------------------------------------------------------------
extern "C" void kernel_launch(void* const* d_in, const int* in_sizes, int n_in,
                              void* d_out, int out_size) {
    const float* hs = (const float*)d_in[0];
    const float* Wq = (const float*)d_in[1];
    const float* Wk = (const float*)d_in[2];
    float* out = (float*)d_out;

    cudaFuncSetAttribute(gemm3, cudaFuncAttributeMaxDynamicSharedMemorySize, GEMM_SMEM);
    cudaFuncSetAttribute(ctx, cudaFuncAttributeMaxDynamicSharedMemorySize, CTX_SMEM);
    cudaFuncSetAttribute(wts, cudaFuncAttributeMaxDynamicSharedMemorySize, WTS_SMEM);

    split_hs<<<2048, 256>>>(hs);
    split_w<<<dim3(16, 16, 2), dim3(32, 8)>>>(Wq, Wk);
    gemm3<<<dim3(32, 4, 2), 256, GEMM_SMEM>>>();
    wts<<<dim3(SS / 16, BB), 512, WTS_SMEM>>>();
    ctx<<<dim3(64, 2, 2), 256, CTX_SMEM>>>(hs, out);
}